// round 15
// baseline (speedup 1.0000x reference)
#include <cuda_runtime.h>
#include <cuda_fp16.h>
#include <cstdint>

// ---------------- problem dims ----------------
#define E_  100
#define B_  1024
#define D_  2048
#define H1_ 512
#define H2_ 256

// ---------------- scratch (__device__ globals; no cudaMalloc allowed) ----
__device__ __half g_xh [(size_t)B_ * D_];          //   4MB
__device__ __half g_w1h[(size_t)E_ * D_ * H1_];    // 210MB
__device__ __half g_w2h[(size_t)E_ * H1_ * H2_];   //  26MB
__device__ __half g_h1h[(size_t)E_ * B_ * H1_];    // 105MB
__device__ int    g_w1done[E_];                    // producer counters

// ---------------- device helpers ----------------
__device__ __forceinline__ uint32_t smem_u32(const void* p) {
    uint32_t a;
    asm("{ .reg .u64 t; cvta.to.shared.u64 t, %1; cvt.u32.u64 %0, t; }" : "=r"(a) : "l"(p));
    return a;
}
__device__ __forceinline__ void cp_async16(uint32_t s, const void* g) {
    asm volatile("cp.async.cg.shared.global [%0], [%1], 16;" :: "r"(s), "l"(g));
}
__device__ __forceinline__ void cp_commit() {
    asm volatile("cp.async.commit_group;" ::: "memory");
}
__device__ __forceinline__ void ldsm4(uint32_t r[4], uint32_t addr) {
    asm volatile("ldmatrix.sync.aligned.m8n8.x4.shared.b16 {%0,%1,%2,%3}, [%4];"
        : "=r"(r[0]), "=r"(r[1]), "=r"(r[2]), "=r"(r[3]) : "r"(addr));
}
__device__ __forceinline__ void ldsm4t(uint32_t& r0, uint32_t& r1, uint32_t& r2, uint32_t& r3,
                                       uint32_t addr) {
    asm volatile("ldmatrix.sync.aligned.m8n8.x4.trans.shared.b16 {%0,%1,%2,%3}, [%4];"
        : "=r"(r0), "=r"(r1), "=r"(r2), "=r"(r3) : "r"(addr));
}
__device__ __forceinline__ void mma_f16(float c[4], const uint32_t a[4], const uint32_t b[2]) {
    asm volatile(
        "mma.sync.aligned.m16n8k16.row.col.f32.f16.f16.f32 "
        "{%0,%1,%2,%3}, {%4,%5,%6,%7}, {%8,%9}, {%0,%1,%2,%3};"
        : "+f"(c[0]), "+f"(c[1]), "+f"(c[2]), "+f"(c[3])
        : "r"(a[0]), "r"(a[1]), "r"(a[2]), "r"(a[3]), "r"(b[0]), "r"(b[1]));
}
__device__ __forceinline__ int ld_acquire(const int* p) {
    int v;
    asm volatile("ld.acquire.gpu.global.b32 %0, [%1];" : "=r"(v) : "l"(p) : "memory");
    return v;
}
__device__ __forceinline__ void red_release_add1(int* p) {
    asm volatile("red.release.gpu.global.add.u32 [%0], 1;" :: "l"(p) : "memory");
}

// ---------------- shared geometry ----------------
#define MT 128
#define NT 128
#define KC 64
#define A_STRIDE 144                 // 64 fp16 = 128B data + 16B pad
#define B_STRIDE 272                 // 128 fp16 = 256B data + 16B pad
#define A_TILE_B (MT * A_STRIDE)     // 18432
#define B_TILE_B (KC * B_STRIDE)     // 17408
#define STAGE_B  (A_TILE_B + B_TILE_B)   // 35840
#define NSTAGE 3
#define SM_TILE_OFF 1024
#define SMEM_TOT (SM_TILE_OFF + NSTAGE * STAGE_B)   // 108544

// producer/consumer split inside the l1 launch
#define CONV_CTAS 8
#define L1_CTAS 32                    // 4 nt x 8 mt
#define CTAS_PER_E (CONV_CTAS + L1_CTAS)

// ================= fused: W1 convert producers + layer-1 GEMM consumers ====
// Per expert e: CTAs [0,8) convert W1[e] fp32->fp16 and release a counter;
// CTAs [8,40) spin until counter==8, then run the R9-proven 128x128 GEMM
// (4 warps, 64x64 warp tile, 3-stage cp.async, 2 CTAs/SM).
__global__ void __launch_bounds__(128, 2)
l1_fused(const float* __restrict__ W1f, __half* __restrict__ W1h,
         const __half* __restrict__ A,
         const float* __restrict__ bias, __half* __restrict__ C,
         const float* __restrict__ b3, float* __restrict__ outF) {
    const int bid = blockIdx.x;
    const int e = bid / CTAS_PER_E;
    const int sub = bid % CTAS_PER_E;
    const int tid = threadIdx.x;

    if (sub < CONV_CTAS) {
        // ---- producer: convert 1/8 of W1[e] (4MB fp32 -> 2MB fp16) ----
        const float4* src = (const float4*)(W1f + (size_t)e * D_ * H1_);
        uint2* dst = (uint2*)(W1h + (size_t)e * D_ * H1_);
        const int per_cta = (D_ * H1_ / 4) / CONV_CTAS;   // 32768 float4
        const int base = sub * per_cta;
        for (int i = tid; i < per_cta; i += 128) {
            float4 v = src[base + i];
            __half2 lo = __floats2half2_rn(v.x, v.y);
            __half2 hi = __floats2half2_rn(v.z, v.w);
            uint2 o;
            o.x = *reinterpret_cast<uint32_t*>(&lo);
            o.y = *reinterpret_cast<uint32_t*>(&hi);
            dst[base + i] = o;
        }
        __threadfence();
        __syncthreads();
        if (tid == 0) red_release_add1(&g_w1done[e]);
        return;
    }

    // ---- consumer: layer-1 GEMM CTA ----
    const int idx = sub - CONV_CTAS;
    const int nt = idx & 3, mt = idx >> 2;
    const int n0 = nt * NT;

    // fold out-init (independent of W1): nt==0 CTAs cover all (b,e) of out
    if (nt == 0) outF[(size_t)(mt * MT + tid) * E_ + e] = b3[e];

    extern __shared__ __align__(128) char smem[];
    float* bias_s = reinterpret_cast<float*>(smem);
    const uint32_t sbase = smem_u32(smem) + SM_TILE_OFF;
    const int lane = tid & 31, warp = tid >> 5;
    const int wm = warp >> 1, wn = warp & 1;

    bias_s[tid] = bias[(size_t)e * H1_ + n0 + tid];

    // wait for this expert's W1 to be converted
    if (tid == 0) {
        while (ld_acquire(&g_w1done[e]) != CONV_CTAS) { __nanosleep(128); }
    }
    __syncthreads();

    const char* Ab = (const char*)(A + (size_t)mt * MT * D_);        // shared x
    const char* Bb = (const char*)(W1h + (size_t)e * D_ * H1_ + n0);
    const int ldaB = D_ * 2;
    const int ldbB = H1_ * 2;

    auto load_stage = [&](int s, int c) {
        const uint32_t st = sbase + s * STAGE_B;
        const char* Ac = Ab + c * KC * 2;
        #pragma unroll
        for (int it = 0; it < 8; it++) {
            int q = tid + it * 128;
            int r = q >> 3, seg = (q & 7) * 16;
            cp_async16(st + r * A_STRIDE + seg, Ac + (size_t)r * ldaB + seg);
        }
        const char* Bc = Bb + (size_t)(c * KC) * ldbB;
        const uint32_t stb = st + A_TILE_B;
        #pragma unroll
        for (int it = 0; it < 8; it++) {
            int q = tid + it * 128;
            int r = q >> 4, seg = (q & 15) * 16;
            cp_async16(stb + r * B_STRIDE + seg, Bc + (size_t)r * ldbB + seg);
        }
    };

    const uint32_t offA = (uint32_t)(lane & 15) * A_STRIDE + (uint32_t)(lane >> 4) * 16;
    const uint32_t offB = (uint32_t)(lane & 15) * B_STRIDE + (uint32_t)(lane >> 4) * 16;
    const uint32_t awoff = (uint32_t)wm * 64 * A_STRIDE + offA;
    const uint32_t bwoff = (uint32_t)wn * 128 + offB;

    uint32_t afr[2][4][4], bfr[2][8][2];
    auto prefetch = [&](uint32_t st, int ks, int buf) {
        const uint32_t sa = st + awoff + (uint32_t)ks * 32;
        #pragma unroll
        for (int i = 0; i < 4; i++)
            ldsm4(afr[buf][i], sa + (uint32_t)i * (16 * A_STRIDE));
        const uint32_t sb = st + A_TILE_B + bwoff + (uint32_t)ks * (16 * B_STRIDE);
        #pragma unroll
        for (int j2 = 0; j2 < 4; j2++) {
            uint32_t r0, r1, r2, r3;
            ldsm4t(r0, r1, r2, r3, sb + (uint32_t)j2 * 32);
            bfr[buf][j2 * 2][0] = r0;     bfr[buf][j2 * 2][1] = r1;
            bfr[buf][j2 * 2 + 1][0] = r2; bfr[buf][j2 * 2 + 1][1] = r3;
        }
    };

    float acc[4][8][4];
    #pragma unroll
    for (int i = 0; i < 4; i++)
        #pragma unroll
        for (int j = 0; j < 8; j++)
            #pragma unroll
            for (int r = 0; r < 4; r++) acc[i][j][r] = 0.0f;

    load_stage(0, 0); cp_commit();
    load_stage(1, 1); cp_commit();
    asm volatile("cp.async.wait_group 1;" ::: "memory");
    __syncthreads();
    prefetch(sbase, 0, 0);

    const int nch = D_ / KC;
    for (int c = 0; c < nch; c++) {
        const uint32_t st = sbase + (c % NSTAGE) * STAGE_B;
        if (c + 2 < nch) { load_stage((c + 2) % NSTAGE, c + 2); cp_commit(); }

        #pragma unroll
        for (int ks = 0; ks < 4; ks++) {
            const int cur = ks & 1;
            if (ks < 3) prefetch(st, ks + 1, cur ^ 1);
            #pragma unroll
            for (int i = 0; i < 4; i++)
                #pragma unroll
                for (int j = 0; j < 8; j++)
                    mma_f16(acc[i][j], afr[cur][i], bfr[cur][j]);
        }

        if (c + 1 < nch) {
            if (c + 2 < nch) { asm volatile("cp.async.wait_group 1;" ::: "memory"); }
            else             { asm volatile("cp.async.wait_group 0;" ::: "memory"); }
            __syncthreads();
            prefetch(sbase + ((c + 1) % NSTAGE) * STAGE_B, 0, 0);
        }
    }

    // epilogue: bias + relu, store fp16 h1
    const int col0 = wn * 64 + (lane & 3) * 2;
    const int mrow0 = mt * MT + wm * 64 + (lane >> 2);
    __half* Ce = C + (size_t)e * (B_ * H1_) + n0;
    #pragma unroll
    for (int i = 0; i < 4; i++) {
        const size_t r0 = (size_t)(mrow0 + i * 16);
        #pragma unroll
        for (int j = 0; j < 8; j++) {
            const int col = col0 + j * 8;
            const float bx = bias_s[col], by = bias_s[col + 1];
            float v0 = fmaxf(acc[i][j][0] + bx, 0.0f);
            float v1 = fmaxf(acc[i][j][1] + by, 0.0f);
            float v2 = fmaxf(acc[i][j][2] + bx, 0.0f);
            float v3 = fmaxf(acc[i][j][3] + by, 0.0f);
            *reinterpret_cast<__half2*>(Ce + r0 * H1_ + col)       = __floats2half2_rn(v0, v1);
            *reinterpret_cast<__half2*>(Ce + (r0 + 8) * H1_ + col) = __floats2half2_rn(v2, v3);
        }
    }
}

// ================= LAYER 2 + fused LAYER 3 (R13-proven, 77us) =============
__global__ void __launch_bounds__(128, 2)
gemm_l2(const __half* __restrict__ A, const __half* __restrict__ Bw,
        const float* __restrict__ bias,
        const float* __restrict__ w3, float* __restrict__ outF,
        int nch, int Ntot) {
    extern __shared__ __align__(128) char smem[];
    float* bias_s = reinterpret_cast<float*>(smem);
    float* w3_s   = reinterpret_cast<float*>(smem + 512);
    const uint32_t sbase = smem_u32(smem) + SM_TILE_OFF;
    const int tid = threadIdx.x, lane = tid & 31, warp = tid >> 5;
    const int wm = warp >> 1, wn = warp & 1;
    const int e = blockIdx.z, mt = blockIdx.y, nt = blockIdx.x;
    const int n0 = nt * NT;
    const int K = nch * KC;

    bias_s[tid] = bias[(size_t)e * Ntot + n0 + tid];
    w3_s[tid]   = w3[(size_t)e * H2_ + n0 + tid];

    const char* Ab = (const char*)(A + ((size_t)e * B_ + (size_t)mt * MT) * K);
    const char* Bb = (const char*)(Bw + (size_t)e * (size_t)K * Ntot + n0);
    const int ldaB = K * 2;
    const int ldbB = Ntot * 2;

    auto load_stage = [&](int s, int c) {
        const uint32_t st = sbase + s * STAGE_B;
        const char* Ac = Ab + c * KC * 2;
        #pragma unroll
        for (int it = 0; it < 8; it++) {
            int q = tid + it * 128;
            int r = q >> 3, seg = (q & 7) * 16;
            cp_async16(st + r * A_STRIDE + seg, Ac + (size_t)r * ldaB + seg);
        }
        const char* Bc = Bb + (size_t)(c * KC) * ldbB;
        const uint32_t stb = st + A_TILE_B;
        #pragma unroll
        for (int it = 0; it < 8; it++) {
            int q = tid + it * 128;
            int r = q >> 4, seg = (q & 15) * 16;
            cp_async16(stb + r * B_STRIDE + seg, Bc + (size_t)r * ldbB + seg);
        }
    };

    const uint32_t offA = (uint32_t)(lane & 15) * A_STRIDE + (uint32_t)(lane >> 4) * 16;
    const uint32_t offB = (uint32_t)(lane & 15) * B_STRIDE + (uint32_t)(lane >> 4) * 16;
    const uint32_t awoff = (uint32_t)wm * 64 * A_STRIDE + offA;
    const uint32_t bwoff = (uint32_t)wn * 128 + offB;

    uint32_t afr[2][4][4], bfr[2][8][2];
    auto prefetch = [&](uint32_t st, int ks, int buf) {
        const uint32_t sa = st + awoff + (uint32_t)ks * 32;
        #pragma unroll
        for (int i = 0; i < 4; i++)
            ldsm4(afr[buf][i], sa + (uint32_t)i * (16 * A_STRIDE));
        const uint32_t sb = st + A_TILE_B + bwoff + (uint32_t)ks * (16 * B_STRIDE);
        #pragma unroll
        for (int j2 = 0; j2 < 4; j2++) {
            uint32_t r0, r1, r2, r3;
            ldsm4t(r0, r1, r2, r3, sb + (uint32_t)j2 * 32);
            bfr[buf][j2 * 2][0] = r0;     bfr[buf][j2 * 2][1] = r1;
            bfr[buf][j2 * 2 + 1][0] = r2; bfr[buf][j2 * 2 + 1][1] = r3;
        }
    };

    float acc[4][8][4];
    #pragma unroll
    for (int i = 0; i < 4; i++)
        #pragma unroll
        for (int j = 0; j < 8; j++)
            #pragma unroll
            for (int r = 0; r < 4; r++) acc[i][j][r] = 0.0f;

    load_stage(0, 0); cp_commit();
    load_stage(1, 1); cp_commit();
    asm volatile("cp.async.wait_group 1;" ::: "memory");
    __syncthreads();
    prefetch(sbase, 0, 0);

    for (int c = 0; c < nch; c++) {
        const uint32_t st = sbase + (c % NSTAGE) * STAGE_B;
        if (c + 2 < nch) { load_stage((c + 2) % NSTAGE, c + 2); cp_commit(); }

        #pragma unroll
        for (int ks = 0; ks < 4; ks++) {
            const int cur = ks & 1;
            if (ks < 3) prefetch(st, ks + 1, cur ^ 1);
            #pragma unroll
            for (int i = 0; i < 4; i++)
                #pragma unroll
                for (int j = 0; j < 8; j++)
                    mma_f16(acc[i][j], afr[cur][i], bfr[cur][j]);
        }

        if (c + 1 < nch) {
            if (c + 2 < nch) { asm volatile("cp.async.wait_group 1;" ::: "memory"); }
            else             { asm volatile("cp.async.wait_group 0;" ::: "memory"); }
            __syncthreads();
            prefetch(sbase + ((c + 1) % NSTAGE) * STAGE_B, 0, 0);
        }
    }

    // fused layer-3 epilogue: partial dot over this CTA's 128 cols
    const int col0 = wn * 64 + (lane & 3) * 2;
    #pragma unroll
    for (int i = 0; i < 4; i++) {
        #pragma unroll
        for (int rr = 0; rr < 2; rr++) {
            float p = 0.0f;
            #pragma unroll
            for (int j = 0; j < 8; j++) {
                const int col = col0 + j * 8;
                float v0 = fmaxf(acc[i][j][rr * 2 + 0] + bias_s[col], 0.0f);
                float v1 = fmaxf(acc[i][j][rr * 2 + 1] + bias_s[col + 1], 0.0f);
                p += v0 * w3_s[col] + v1 * w3_s[col + 1];
            }
            p += __shfl_xor_sync(0xFFFFFFFFu, p, 1);
            p += __shfl_xor_sync(0xFFFFFFFFu, p, 2);
            if ((lane & 3) == 0) {
                const int b = mt * MT + wm * 64 + i * 16 + rr * 8 + (lane >> 2);
                atomicAdd(&outF[(size_t)b * E_ + e], p);
            }
        }
    }
}

// ---------------- aux kernels ----------------
__global__ void reset_flags_kernel() {
    if (threadIdx.x < E_) g_w1done[threadIdx.x] = 0;
}
__global__ void f32_to_f16_dual(const float4* __restrict__ in1, uint2* __restrict__ out1, long n1,
                                const float4* __restrict__ in2, uint2* __restrict__ out2, long n2) {
    long i = blockIdx.x * (long)blockDim.x + threadIdx.x;
    const float4* in; uint2* out; long k;
    if (i < n1) { in = in1; out = out1; k = i; }
    else if (i < n1 + n2) { in = in2; out = out2; k = i - n1; }
    else return;
    float4 v = in[k];
    __half2 lo = __floats2half2_rn(v.x, v.y);
    __half2 hi = __floats2half2_rn(v.z, v.w);
    uint2 o;
    o.x = *reinterpret_cast<uint32_t*>(&lo);
    o.y = *reinterpret_cast<uint32_t*>(&hi);
    out[k] = o;
}

// ---------------- host ----------------
extern "C" void kernel_launch(void* const* d_in, const int* in_sizes, int n_in,
                              void* d_out, int out_size) {
    const float* x  = (const float*)d_in[0];
    const float* W1 = (const float*)d_in[1];
    const float* b1 = (const float*)d_in[2];
    const float* W2 = (const float*)d_in[3];
    const float* b2 = (const float*)d_in[4];
    const float* W3 = (const float*)d_in[5];
    const float* b3 = (const float*)d_in[6];
    float* out = (float*)d_out;

    __half *xh, *w1h, *w2h, *h1h;
    cudaGetSymbolAddress((void**)&xh,  g_xh);
    cudaGetSymbolAddress((void**)&w1h, g_w1h);
    cudaGetSymbolAddress((void**)&w2h, g_w2h);
    cudaGetSymbolAddress((void**)&h1h, g_h1h);

    cudaFuncSetAttribute(l1_fused, cudaFuncAttributeMaxDynamicSharedMemorySize, SMEM_TOT);
    cudaFuncSetAttribute(gemm_l2,  cudaFuncAttributeMaxDynamicSharedMemorySize, SMEM_TOT);

    // reset producer counters (replay-safe)
    reset_flags_kernel<<<1, 128>>>();

    // pre-convert x and W2 (small; W1 converts inside l1_fused)
    {
        long n4x  = (long)B_ * D_ / 4;
        long n4w2 = (long)E_ * H1_ * H2_ / 4;
        f32_to_f16_dual<<<(unsigned)((n4x + n4w2 + 255) / 256), 256>>>(
            (const float4*)x,  (uint2*)xh,  n4x,
            (const float4*)W2, (uint2*)w2h, n4w2);
    }

    // fused W1-convert + layer 1 (+ out init): per expert 8 producer CTAs
    // then 32 GEMM CTAs; grid-ordered overlap hides the 629MB convert
    {
        l1_fused<<<E_ * CTAS_PER_E, 128, SMEM_TOT>>>(
            W1, w1h, xh, b1, h1h, b3, out);
    }
    // layer 2 + fused layer 3 (atomic accumulation into b3-initialized out)
    {
        dim3 grid(H2_ / NT, B_ / MT, E_);   // (2, 8, 100)
        gemm_l2<<<grid, 128, SMEM_TOT>>>(
            h1h, w2h, b2, W3, out,
            H1_ / KC, /*Ntot=*/H2_);
    }
}

// round 16
// speedup vs baseline: 1.5243x; 1.5243x over previous
#include <cuda_runtime.h>
#include <cuda_fp16.h>
#include <cstdint>

// ---------------- problem dims ----------------
#define E_  100
#define B_  1024
#define D_  2048
#define H1_ 512
#define H2_ 256

// ---------------- scratch (__device__ globals; no cudaMalloc allowed) ----
__device__ __half g_xh [(size_t)B_ * D_];          //   4MB
__device__ __half g_w1h[(size_t)E_ * D_ * H1_];    // 210MB
__device__ __half g_w2h[(size_t)E_ * H1_ * H2_];   //  26MB
__device__ __half g_h1h[(size_t)E_ * B_ * H1_];    // 105MB

// ---------------- device helpers ----------------
__device__ __forceinline__ uint32_t smem_u32(const void* p) {
    uint32_t a;
    asm("{ .reg .u64 t; cvta.to.shared.u64 t, %1; cvt.u32.u64 %0, t; }" : "=r"(a) : "l"(p));
    return a;
}
__device__ __forceinline__ void cp_async16(uint32_t s, const void* g) {
    asm volatile("cp.async.cg.shared.global [%0], [%1], 16;" :: "r"(s), "l"(g));
}
__device__ __forceinline__ void cp_commit() {
    asm volatile("cp.async.commit_group;" ::: "memory");
}
__device__ __forceinline__ void ldsm4(uint32_t r[4], uint32_t addr) {
    asm volatile("ldmatrix.sync.aligned.m8n8.x4.shared.b16 {%0,%1,%2,%3}, [%4];"
        : "=r"(r[0]), "=r"(r[1]), "=r"(r[2]), "=r"(r[3]) : "r"(addr));
}
__device__ __forceinline__ void ldsm4t(uint32_t& r0, uint32_t& r1, uint32_t& r2, uint32_t& r3,
                                       uint32_t addr) {
    asm volatile("ldmatrix.sync.aligned.m8n8.x4.trans.shared.b16 {%0,%1,%2,%3}, [%4];"
        : "=r"(r0), "=r"(r1), "=r"(r2), "=r"(r3) : "r"(addr));
}
__device__ __forceinline__ void mma_f16(float c[4], const uint32_t a[4], const uint32_t b[2]) {
    asm volatile(
        "mma.sync.aligned.m16n8k16.row.col.f32.f16.f16.f32 "
        "{%0,%1,%2,%3}, {%4,%5,%6,%7}, {%8,%9}, {%0,%1,%2,%3};"
        : "+f"(c[0]), "+f"(c[1]), "+f"(c[2]), "+f"(c[3])
        : "r"(a[0]), "r"(a[1]), "r"(a[2]), "r"(a[3]), "r"(b[0]), "r"(b[1]));
}

// ---------------- shared geometry (R9/R13-proven) ----------------
#define MT 128
#define NT 128
#define KC 64
#define A_STRIDE 144                 // 64 fp16 = 128B data + 16B pad
#define B_STRIDE 272                 // 128 fp16 = 256B data + 16B pad
#define A_TILE_B (MT * A_STRIDE)     // 18432
#define B_TILE_B (KC * B_STRIDE)     // 17408
#define STAGE_B  (A_TILE_B + B_TILE_B)   // 35840
#define NSTAGE 3
#define SM_TILE_OFF 1024             // bias[128]f32 @0, w3_s[128]f32 @512
#define SMEM_TOT (SM_TILE_OFF + NSTAGE * STAGE_B)   // 108544

// ---------------- GEMM: 128x128 CTA, 4 warps (2m x 2n), warp tile 64x64 ---
// FUSEL3: epilogue computes relu(acc+bias) . w3 per row and atomically
// accumulates into outF[b*E+e] (pre-initialized to b3 by the l1 kernel).
// !FUSEL3 (layer1): nt==0 CTAs also initialize outF rows to b3 (aux = b3).
template <bool FUSEL3>
__global__ void __launch_bounds__(128, 2)
gemm_f16(const __half* __restrict__ A, const __half* __restrict__ Bw,
         const float* __restrict__ bias, __half* __restrict__ C,
         const float* __restrict__ aux, float* __restrict__ outF,
         int nch, int ArowsPerE, int Ntot, unsigned long long strideCe) {
    extern __shared__ __align__(128) char smem[];
    float* bias_s = reinterpret_cast<float*>(smem);
    float* w3_s   = reinterpret_cast<float*>(smem + 512);
    const uint32_t sbase = smem_u32(smem) + SM_TILE_OFF;
    const int tid = threadIdx.x, lane = tid & 31, warp = tid >> 5;
    const int wm = warp >> 1, wn = warp & 1;
    const int e = blockIdx.z, mt = blockIdx.y, nt = blockIdx.x;
    const int n0 = nt * NT;
    const int K = nch * KC;

    bias_s[tid] = bias[(size_t)e * Ntot + n0 + tid];
    if (FUSEL3) w3_s[tid] = aux[(size_t)e * H2_ + n0 + tid];
    else if (nt == 0) outF[(size_t)(mt * MT + tid) * E_ + e] = aux[e];

    const char* Ab = (const char*)(A + ((size_t)e * ArowsPerE + (size_t)mt * MT) * K);
    const char* Bb = (const char*)(Bw + (size_t)e * (size_t)K * Ntot + n0);
    const int ldaB = K * 2;
    const int ldbB = Ntot * 2;

    auto load_stage = [&](int s, int c) {
        const uint32_t st = sbase + s * STAGE_B;
        const char* Ac = Ab + c * KC * 2;
        #pragma unroll
        for (int it = 0; it < 8; it++) {
            int q = tid + it * 128;              // 0..1023 (128 rows x 8 segs)
            int r = q >> 3, seg = (q & 7) * 16;
            cp_async16(st + r * A_STRIDE + seg, Ac + (size_t)r * ldaB + seg);
        }
        const char* Bc = Bb + (size_t)(c * KC) * ldbB;
        const uint32_t stb = st + A_TILE_B;
        #pragma unroll
        for (int it = 0; it < 8; it++) {
            int q = tid + it * 128;              // 0..1023 (64 rows x 16 segs)
            int r = q >> 4, seg = (q & 15) * 16;
            cp_async16(stb + r * B_STRIDE + seg, Bc + (size_t)r * ldbB + seg);
        }
    };

    // per-lane ldmatrix offsets (bytes)
    const uint32_t offA = (uint32_t)(lane & 15) * A_STRIDE + (uint32_t)(lane >> 4) * 16;
    const uint32_t offB = (uint32_t)(lane & 15) * B_STRIDE + (uint32_t)(lane >> 4) * 16;
    const uint32_t awoff = (uint32_t)wm * 64 * A_STRIDE + offA;
    const uint32_t bwoff = (uint32_t)wn * 128 + offB;         // wn*64 cols * 2B

    // double-buffered fragments: A 4 m16-tiles, B 8 n8-blocks
    uint32_t afr[2][4][4], bfr[2][8][2];

    auto prefetch = [&](uint32_t st, int ks, int buf) {
        const uint32_t sa = st + awoff + (uint32_t)ks * 32;
        #pragma unroll
        for (int i = 0; i < 4; i++)
            ldsm4(afr[buf][i], sa + (uint32_t)i * (16 * A_STRIDE));
        const uint32_t sb = st + A_TILE_B + bwoff + (uint32_t)ks * (16 * B_STRIDE);
        #pragma unroll
        for (int j2 = 0; j2 < 4; j2++) {
            uint32_t r0, r1, r2, r3;
            ldsm4t(r0, r1, r2, r3, sb + (uint32_t)j2 * 32);
            bfr[buf][j2 * 2][0] = r0;     bfr[buf][j2 * 2][1] = r1;
            bfr[buf][j2 * 2 + 1][0] = r2; bfr[buf][j2 * 2 + 1][1] = r3;
        }
    };

    float acc[4][8][4];
    #pragma unroll
    for (int i = 0; i < 4; i++)
        #pragma unroll
        for (int j = 0; j < 8; j++)
            #pragma unroll
            for (int r = 0; r < 4; r++) acc[i][j][r] = 0.0f;

    // ---- prologue ----
    load_stage(0, 0); cp_commit();
    load_stage(1, 1); cp_commit();
    asm volatile("cp.async.wait_group 1;" ::: "memory");
    __syncthreads();
    prefetch(sbase, 0, 0);

    // ---- mainloop ----
    for (int c = 0; c < nch; c++) {
        const uint32_t st = sbase + (c % NSTAGE) * STAGE_B;
        if (c + 2 < nch) { load_stage((c + 2) % NSTAGE, c + 2); cp_commit(); }

        #pragma unroll
        for (int ks = 0; ks < 4; ks++) {
            const int cur = ks & 1;
            if (ks < 3) prefetch(st, ks + 1, cur ^ 1);
            #pragma unroll
            for (int i = 0; i < 4; i++)
                #pragma unroll
                for (int j = 0; j < 8; j++)
                    mma_f16(acc[i][j], afr[cur][i], bfr[cur][j]);
        }

        if (c + 1 < nch) {
            if (c + 2 < nch) { asm volatile("cp.async.wait_group 1;" ::: "memory"); }
            else             { asm volatile("cp.async.wait_group 0;" ::: "memory"); }
            __syncthreads();
            prefetch(sbase + ((c + 1) % NSTAGE) * STAGE_B, 0, 0);
        }
    }

    const int col0 = wn * 64 + (lane & 3) * 2;

    if (FUSEL3) {
        // ---- fused layer-3 epilogue: partial dot over this CTA's 128 cols --
        #pragma unroll
        for (int i = 0; i < 4; i++) {
            #pragma unroll
            for (int rr = 0; rr < 2; rr++) {
                float p = 0.0f;
                #pragma unroll
                for (int j = 0; j < 8; j++) {
                    const int col = col0 + j * 8;
                    float v0 = fmaxf(acc[i][j][rr * 2 + 0] + bias_s[col], 0.0f);
                    float v1 = fmaxf(acc[i][j][rr * 2 + 1] + bias_s[col + 1], 0.0f);
                    p += v0 * w3_s[col] + v1 * w3_s[col + 1];
                }
                p += __shfl_xor_sync(0xFFFFFFFFu, p, 1);
                p += __shfl_xor_sync(0xFFFFFFFFu, p, 2);
                if ((lane & 3) == 0) {
                    const int b = mt * MT + wm * 64 + i * 16 + rr * 8 + (lane >> 2);
                    atomicAdd(&outF[(size_t)b * E_ + e], p);
                }
            }
        }
        return;
    }

    // ---- epilogue: bias + relu, store fp16 ----
    const int mrow0 = mt * MT + wm * 64 + (lane >> 2);
    __half* Ce = C + (size_t)e * strideCe + n0;
    #pragma unroll
    for (int i = 0; i < 4; i++) {
        const size_t r0 = (size_t)(mrow0 + i * 16);
        #pragma unroll
        for (int j = 0; j < 8; j++) {
            const int col = col0 + j * 8;
            const float bx = bias_s[col], by = bias_s[col + 1];
            float v0 = fmaxf(acc[i][j][0] + bx, 0.0f);
            float v1 = fmaxf(acc[i][j][1] + by, 0.0f);
            float v2 = fmaxf(acc[i][j][2] + bx, 0.0f);
            float v3 = fmaxf(acc[i][j][3] + by, 0.0f);
            *reinterpret_cast<__half2*>(Ce + r0 * Ntot + col)       = __floats2half2_rn(v0, v1);
            *reinterpret_cast<__half2*>(Ce + (r0 + 8) * Ntot + col) = __floats2half2_rn(v2, v3);
        }
    }
}

// ---------------- single mega convert: W1 + x + W2 in ONE launch ----------
#define N4_W1 ((long)E_ * D_ * H1_ / 4)   // 26,214,400
#define N4_X  ((long)B_ * D_ / 4)         //    524,288
#define N4_W2 ((long)E_ * H1_ * H2_ / 4)  //  3,276,800

__global__ void convert_all(const float4* __restrict__ w1, uint2* __restrict__ w1h,
                            const float4* __restrict__ x,  uint2* __restrict__ xh,
                            const float4* __restrict__ w2, uint2* __restrict__ w2h) {
    long i = blockIdx.x * (long)blockDim.x + threadIdx.x;
    const float4* in; uint2* out; long k;
    if (i < N4_W1)              { in = w1; out = w1h; k = i; }
    else if (i < N4_W1 + N4_X)  { in = x;  out = xh;  k = i - N4_W1; }
    else if (i < N4_W1 + N4_X + N4_W2) { in = w2; out = w2h; k = i - N4_W1 - N4_X; }
    else return;
    float4 v = in[k];
    __half2 lo = __floats2half2_rn(v.x, v.y);
    __half2 hi = __floats2half2_rn(v.z, v.w);
    uint2 o;
    o.x = *reinterpret_cast<uint32_t*>(&lo);
    o.y = *reinterpret_cast<uint32_t*>(&hi);
    out[k] = o;
}

// ---------------- host ----------------
extern "C" void kernel_launch(void* const* d_in, const int* in_sizes, int n_in,
                              void* d_out, int out_size) {
    const float* x  = (const float*)d_in[0];
    const float* W1 = (const float*)d_in[1];
    const float* b1 = (const float*)d_in[2];
    const float* W2 = (const float*)d_in[3];
    const float* b2 = (const float*)d_in[4];
    const float* W3 = (const float*)d_in[5];
    const float* b3 = (const float*)d_in[6];
    float* out = (float*)d_out;

    __half *xh, *w1h, *w2h, *h1h;
    cudaGetSymbolAddress((void**)&xh,  g_xh);
    cudaGetSymbolAddress((void**)&w1h, g_w1h);
    cudaGetSymbolAddress((void**)&w2h, g_w2h);
    cudaGetSymbolAddress((void**)&h1h, g_h1h);

    cudaFuncSetAttribute(gemm_f16<false>, cudaFuncAttributeMaxDynamicSharedMemorySize, SMEM_TOT);
    cudaFuncSetAttribute(gemm_f16<true>,  cudaFuncAttributeMaxDynamicSharedMemorySize, SMEM_TOT);

    // 1) one convert launch for W1 + x + W2
    {
        long total = N4_W1 + N4_X + N4_W2;
        convert_all<<<(unsigned)((total + 255) / 256), 256>>>(
            (const float4*)W1, (uint2*)w1h,
            (const float4*)x,  (uint2*)xh,
            (const float4*)W2, (uint2*)w2h);
    }

    // 2) layer 1: per-expert [1024,2048] x [2048,512], relu -> h1 (fp16).
    //    nt==0 CTAs also initialize out[b*E+e] = b3[e].
    {
        dim3 grid(H1_ / NT, B_ / MT, E_);   // (4, 8, 100)
        gemm_f16<false><<<grid, 128, SMEM_TOT>>>(
            xh, w1h, b1, h1h, b3, out,
            D_ / KC, /*ArowsPerE=*/0, /*Ntot=*/H1_,
            (unsigned long long)B_ * H1_);
    }

    // 3) layer 2 + fused layer 3: relu(h1 W2 + b2) . W3 accumulated into out
    {
        dim3 grid(H2_ / NT, B_ / MT, E_);   // (2, 8, 100)
        gemm_f16<true><<<grid, 128, SMEM_TOT>>>(
            h1h, w2h, b2, nullptr, W3, out,
            H1_ / KC, /*ArowsPerE=*/B_, /*Ntot=*/H2_,
            0ULL);
    }
}